// round 15
// baseline (speedup 1.0000x reference)
#include <cuda_runtime.h>
#include <cuda_bf16.h>
#include <math.h>
#include <stdint.h>

// ---------------- model dims ----------------
#define NLAYER 4
#define DMODEL 1024
#define NHEAD  16
#define DHEAD  64
#define NTOK   1536
#define NCTX   512
#define VOCAB  8192
#define FFI    2730          // GEGLU inner
#define FF2    5460          // 2*FFI
#define FFIP   2752          // FFI padded to 64
#define NKPAD_SA 1600        // 25*64 >= NTOK+1
#define NKPAD_CA 576         // 9*64  >= NCTX+1

// ---------------- weight scratch offsets (padded, transposed [n][k] bf16) ----------------
#define W_WQ    0ull
#define W_WKV   1048576ull
#define W_WO    3145728ull
#define W_CWQ   4194304ull
#define W_CWKV  5242880ull
#define W_CWO   7340032ull
#define W_FF1   8388608ull
#define W_FF2   14024704ull
#define LBLK    16842752ull
#define W_LOG   67371008ull
#define WTOT    75759616ull

// ---------------- scratch (device globals; no allocation allowed) ----------------
__device__ float g_H  [NTOK * DMODEL];
__device__ float g_QKV[NTOK * 3 * DMODEL];
__device__ float g_Q  [NTOK * DMODEL];
__device__ float g_KV [NCTX * 2 * DMODEL];
__device__ float g_HH [NTOK * FF2];

__device__ __align__(128) __nv_bfloat16 g_WH[WTOT];
__device__ __align__(128) __nv_bfloat16 g_WL[WTOT];
__device__ __align__(128) __nv_bfloat16 g_XNh[NTOK * DMODEL],  g_XNl[NTOK * DMODEL];
__device__ __align__(128) __nv_bfloat16 g_CTXh[NCTX * DMODEL], g_CTXl[NCTX * DMODEL];
__device__ __align__(128) __nv_bfloat16 g_Oh[NTOK * DMODEL],   g_Ol[NTOK * DMODEL];
__device__ __align__(128) __nv_bfloat16 g_GNh[NTOK * FFIP],    g_GNl[NTOK * FFIP];
// attention operands, bf16 hi/lo
__device__ __align__(128) __nv_bfloat16 g_Qbh[NHEAD * NTOK * DHEAD], g_Qbl[NHEAD * NTOK * DHEAD];
__device__ __align__(128) __nv_bfloat16 g_Kbh[NHEAD * NKPAD_SA * DHEAD], g_Kbl[NHEAD * NKPAD_SA * DHEAD];
__device__ __align__(128) __nv_bfloat16 g_Vbh[NHEAD * NKPAD_SA * DHEAD], g_Vbl[NHEAD * NKPAD_SA * DHEAD];

// ---------------- helpers ----------------
__device__ __forceinline__ uint32_t smem_u32(const void* p) {
    uint32_t a;
    asm("{ .reg .u64 t; cvta.to.shared.u64 t, %1; cvt.u32.u64 %0, t; }" : "=r"(a) : "l"(p));
    return a;
}
__device__ __forceinline__ void split2(float f0, float f1, uint32_t& hi, uint32_t& lo) {
    __nv_bfloat16 h0 = __float2bfloat16(f0), h1 = __float2bfloat16(f1);
    float r0 = f0 - __bfloat162float(h0), r1 = f1 - __bfloat162float(h1);
    __nv_bfloat16 l0 = __float2bfloat16(r0), l1 = __float2bfloat16(r1);
    hi = (uint32_t)__bfloat16_as_ushort(h0) | ((uint32_t)__bfloat16_as_ushort(h1) << 16);
    lo = (uint32_t)__bfloat16_as_ushort(l0) | ((uint32_t)__bfloat16_as_ushort(l1) << 16);
}
__device__ __forceinline__ void ldsm4(uint32_t* r, uint32_t addr) {
    asm volatile("ldmatrix.sync.aligned.m8n8.x4.shared.b16 {%0,%1,%2,%3}, [%4];"
                 : "=r"(r[0]), "=r"(r[1]), "=r"(r[2]), "=r"(r[3]) : "r"(addr));
}
__device__ __forceinline__ void ldsm4t(uint32_t* r, uint32_t addr) {
    asm volatile("ldmatrix.sync.aligned.m8n8.x4.trans.shared.b16 {%0,%1,%2,%3}, [%4];"
                 : "=r"(r[0]), "=r"(r[1]), "=r"(r[2]), "=r"(r[3]) : "r"(addr));
}
__device__ __forceinline__ void mma16816(float* c, const uint32_t* a, uint32_t b0, uint32_t b1) {
    asm volatile(
        "mma.sync.aligned.m16n8k16.row.col.f32.bf16.bf16.f32 "
        "{%0,%1,%2,%3}, {%4,%5,%6,%7}, {%8,%9}, {%0,%1,%2,%3};"
        : "+f"(c[0]), "+f"(c[1]), "+f"(c[2]), "+f"(c[3])
        : "r"(a[0]), "r"(a[1]), "r"(a[2]), "r"(a[3]), "r"(b0), "r"(b1));
}
__device__ __forceinline__ void cp16(uint32_t s, const void* g) {
    asm volatile("cp.async.cg.shared.global [%0], [%1], 16;\n" :: "r"(s), "l"(g));
}

// ---------------- fused weight convert: all 33 weights in ONE launch ----------------
struct ConvEnt {
    const float* W;
    long long off;
    int K, N, kpad, tiles_n, tileStart;
};
struct ConvTab { ConvEnt e[33]; int cnt; };

__global__ void convw_all_kernel(ConvTab tab, __nv_bfloat16* __restrict__ WH,
                                 __nv_bfloat16* __restrict__ WL) {
    __shared__ float t[32][33];
    int b = blockIdx.x;
    int i = 0;
    #pragma unroll 1
    while (i + 1 < tab.cnt && tab.e[i + 1].tileStart <= b) i++;
    const ConvEnt en = tab.e[i];
    int local = b - en.tileStart;
    int nb = (local % en.tiles_n) * 32;
    int kb = (local / en.tiles_n) * 32;
    __nv_bfloat16* TH = WH + en.off;
    __nv_bfloat16* TL = WL + en.off;

    int tid = threadIdx.x;
    int tx = tid & 31, ty = tid >> 5;
    #pragma unroll
    for (int r = 0; r < 4; r++) {
        int k = kb + ty + 8 * r, n = nb + tx;
        t[ty + 8 * r][tx] = (k < en.K && n < en.N) ? en.W[(size_t)k * en.N + n] : 0.f;
    }
    __syncthreads();
    int nrow = tid >> 3, kp = tid & 7;
    #pragma unroll
    for (int w = 0; w < 2; w++) {
        int kk = (kp + 8 * w) * 2;
        float f0 = t[kk][nrow], f1 = t[kk + 1][nrow];
        uint32_t hi, lo;
        split2(f0, f1, hi, lo);
        size_t o = (size_t)(nb + nrow) * en.kpad + kb + kk;
        *(uint32_t*)&TH[o] = hi;
        *(uint32_t*)&TL[o] = lo;
    }
}

// ---------------- tensor-core GEMM: 128x64 CTA tile, BK=32, 3-stage ring, 3 CTAs/SM ----
// smem/buffer: Ah 8K | Al 8K | Bh 4K | Bl 4K = 24KB; 3 buffers = 72KB.
// 8 warps, warp tile 32x32; 64B row pitch, XOR field (row>>1)&3 (bank-conflict-free).
__global__ __launch_bounds__(256, 3)
void gemm_bf16_kernel(const __nv_bfloat16* __restrict__ AH, const __nv_bfloat16* __restrict__ AL,
                      const __nv_bfloat16* __restrict__ BH, const __nv_bfloat16* __restrict__ BL,
                      float* __restrict__ C, int M, int N, int lda, int ldb,
                      int ktiles, int addC) {
    extern __shared__ char smraw[];
    uint32_t sbase = smem_u32(smraw);
    int tid = threadIdx.x, warp = tid >> 5, lane = tid & 31;
    int wm = (warp >> 1) * 32, wn = (warp & 1) * 32;
    int m0 = blockIdx.y * 128, n0 = blockIdx.x * 64;

    float acc[2][4][4];
    #pragma unroll
    for (int mi = 0; mi < 2; mi++)
        #pragma unroll
        for (int ni = 0; ni < 4; ni++)
            acc[mi][ni][0] = acc[mi][ni][1] = acc[mi][ni][2] = acc[mi][ni][3] = 0.f;

    int srow = tid >> 2, skc = tid & 3;    // 64 rows x 4 chunks per pass

    auto stage = [&](int t, int buf) {
        int k0 = t << 5;
        uint32_t sb = sbase + (uint32_t)buf * 24576u;
        #pragma unroll
        for (int i = 0; i < 2; i++) {      // A: rows srow, srow+64
            int row = srow + i * 64;
            uint32_t off = (uint32_t)row * 64 + (uint32_t)((skc ^ ((row >> 1) & 3)) << 4);
            size_t ao = (size_t)(m0 + row) * lda + k0 + skc * 8;
            cp16(sb + off,        AH + ao);
            cp16(sb + 8192 + off, AL + ao);
        }
        {                                   // B: rows srow (0..63)
            int row = srow;
            uint32_t off = (uint32_t)row * 64 + (uint32_t)((skc ^ ((row >> 1) & 3)) << 4);
            size_t bo = (size_t)(n0 + row) * ldb + k0 + skc * 8;
            cp16(sb + 16384 + off, BH + bo);
            cp16(sb + 20480 + off, BL + bo);
        }
        asm volatile("cp.async.commit_group;\n" ::: "memory");
    };

    stage(0, 0);
    if (ktiles > 1) stage(1, 1);
    int bt = 0;
    for (int t = 0; t < ktiles; t++) {
        asm volatile("cp.async.wait_group 1;\n" ::: "memory");
        __syncthreads();
        if (t + 2 < ktiles) {
            int nb = bt + 2;
            if (nb >= 3) nb -= 3;
            stage(t + 2, nb);
        }

        uint32_t aHb = sbase + (uint32_t)bt * 24576u;
        uint32_t aLb = aHb + 8192, bHb = aHb + 16384, bLb = aHb + 20480;
        #pragma unroll
        for (int ks = 0; ks < 2; ks++) {
            uint32_t ah[2][4], al[2][4];
            #pragma unroll
            for (int mi = 0; mi < 2; mi++) {
                int row = wm + mi * 16 + (lane & 15);
                int c = ks * 2 + (lane >> 4);
                uint32_t off = (uint32_t)row * 64 + (uint32_t)((c ^ ((row >> 1) & 3)) << 4);
                ldsm4(ah[mi], aHb + off);
                ldsm4(al[mi], aLb + off);
            }
            #pragma unroll
            for (int np = 0; np < 2; np++) {
                uint32_t bh[4], bl[4];
                int row = wn + np * 16 + (lane & 15);
                int c = ks * 2 + (lane >> 4);
                uint32_t off = (uint32_t)row * 64 + (uint32_t)((c ^ ((row >> 1) & 3)) << 4);
                ldsm4(bh, bHb + off);
                ldsm4(bl, bLb + off);
                #pragma unroll
                for (int mi = 0; mi < 2; mi++) {
                    mma16816(acc[mi][2 * np],     ah[mi], bh[0], bh[2]);
                    mma16816(acc[mi][2 * np],     al[mi], bh[0], bh[2]);
                    mma16816(acc[mi][2 * np],     ah[mi], bl[0], bl[2]);
                    mma16816(acc[mi][2 * np + 1], ah[mi], bh[1], bh[3]);
                    mma16816(acc[mi][2 * np + 1], al[mi], bh[1], bh[3]);
                    mma16816(acc[mi][2 * np + 1], ah[mi], bl[1], bl[3]);
                }
            }
        }
        bt = (bt + 1 == 3) ? 0 : bt + 1;
    }

    int gid = lane >> 2, tig = lane & 3;
    #pragma unroll
    for (int mi = 0; mi < 2; mi++) {
        #pragma unroll
        for (int ni = 0; ni < 4; ni++) {
            int row = m0 + wm + mi * 16 + gid;
            int col = n0 + wn + ni * 8 + tig * 2;
            if (col + 1 < N && row < M) {
                float* cp = &C[(size_t)row * N + col];
                float2 v = make_float2(acc[mi][ni][0], acc[mi][ni][1]);
                if (addC) { float2 o = *(float2*)cp; v.x += o.x; v.y += o.y; }
                *(float2*)cp = v;
                float* cp8 = cp + 8 * (size_t)N;
                float2 w = make_float2(acc[mi][ni][2], acc[mi][ni][3]);
                if (addC) { float2 o = *(float2*)cp8; w.x += o.x; w.y += o.y; }
                *(float2*)cp8 = w;
            }
        }
    }
}

// ---------------- embeddings ----------------
__global__ void embed_img_kernel(const int* __restrict__ ids, const float* __restrict__ te,
                                 const float* __restrict__ pe, float* __restrict__ out) {
    int i = blockIdx.x * blockDim.x + threadIdx.x;
    if (i >= NTOK * DMODEL) return;
    int n = i >> 10, d = i & 1023;
    out[i] = te[(size_t)ids[n] * DMODEL + d] + pe[i];
}
__global__ void embed_ctx_kernel(const int* __restrict__ ids, const float* __restrict__ te,
                                 const float* __restrict__ pe,
                                 __nv_bfloat16* __restrict__ Yh, __nv_bfloat16* __restrict__ Yl) {
    int p = blockIdx.x * blockDim.x + threadIdx.x;
    if (p >= NCTX * DMODEL / 2) return;
    int i = p * 2;
    int n = i >> 10, d = i & 1023;
    const float* row = te + (size_t)ids[n] * DMODEL;
    float f0 = row[d] + pe[i];
    float f1 = row[d + 1] + pe[i + 1];
    uint32_t hi, lo;
    split2(f0, f1, hi, lo);
    *(uint32_t*)&Yh[i] = hi;
    *(uint32_t*)&Yl[i] = lo;
}

// ---------------- LayerNorm: one WARP per 1024-dim row ----------------
__global__ void ln_kernel(const float* __restrict__ X, const float* __restrict__ g,
                          __nv_bfloat16* __restrict__ Yh, __nv_bfloat16* __restrict__ Yl) {
    int row = blockIdx.x * 8 + (threadIdx.x >> 5);
    int lane = threadIdx.x & 31;
    const float* x = X + (size_t)row * DMODEL;
    float4 v[8];
    float s1 = 0.f, s2 = 0.f;
    #pragma unroll
    for (int j = 0; j < 8; j++) {
        v[j] = *(const float4*)&x[j * 128 + lane * 4];
        s1 += v[j].x + v[j].y + v[j].z + v[j].w;
        s2 += v[j].x * v[j].x + v[j].y * v[j].y + v[j].z * v[j].z + v[j].w * v[j].w;
    }
    #pragma unroll
    for (int s = 16; s; s >>= 1) {
        s1 += __shfl_xor_sync(0xffffffffu, s1, s);
        s2 += __shfl_xor_sync(0xffffffffu, s2, s);
    }
    float mean = s1 / DMODEL;
    float var  = s2 / DMODEL - mean * mean;
    float inv  = rsqrtf(var + 1e-5f);
    #pragma unroll
    for (int j = 0; j < 8; j++) {
        const float4 g4 = *(const float4*)&g[j * 128 + lane * 4];
        float y0 = (v[j].x - mean) * inv * g4.x;
        float y1 = (v[j].y - mean) * inv * g4.y;
        float y2 = (v[j].z - mean) * inv * g4.z;
        float y3 = (v[j].w - mean) * inv * g4.w;
        uint32_t h0, l0, h1, l1;
        split2(y0, y1, h0, l0);
        split2(y2, y3, h1, l1);
        size_t o = (size_t)row * DMODEL + j * 128 + lane * 4;
        *(uint2*)&Yh[o] = make_uint2(h0, h1);
        *(uint2*)&Yl[o] = make_uint2(l0, l1);
    }
}

// ---------------- fused GEGLU + LayerNorm -> bf16 hi/lo [row][FFIP] ----------------
__global__ void geglu_ln_kernel(const float* __restrict__ HH, const float* __restrict__ g2,
                                __nv_bfloat16* __restrict__ Yh, __nv_bfloat16* __restrict__ Yl) {
    int row = blockIdx.x;
    const float* h = HH + (size_t)row * FF2;
    int tid = threadIdx.x;
    __shared__ float buf[FFI];
    __shared__ float red[512];
    float s1 = 0.f, s2 = 0.f;
    for (int c = tid; c < FFI; c += 256) {
        float a = h[c], gate = h[FFI + c];
        float v = gate * (0.5f * a * (1.0f + erff(a * 0.70710678118654752f)));
        buf[c] = v; s1 += v; s2 += v * v;
    }
    red[tid] = s1; red[256 + tid] = s2;
    __syncthreads();
    for (int s = 128; s > 0; s >>= 1) {
        if (tid < s) { red[tid] += red[tid + s]; red[256 + tid] += red[256 + tid + s]; }
        __syncthreads();
    }
    float mean = red[0] / FFI;
    float var  = red[256] / FFI - mean * mean;
    float inv  = rsqrtf(var + 1e-5f);
    for (int q = tid; q < FFIP / 4; q += 256) {
        int c = q * 4;
        float y[4];
        #pragma unroll
        for (int j = 0; j < 4; j++) {
            int cc = c + j;
            y[j] = (cc < FFI) ? (buf[cc] - mean) * inv * g2[cc] : 0.f;
        }
        uint32_t h0, l0, h1, l1;
        split2(y[0], y[1], h0, l0);
        split2(y[2], y[3], h1, l1);
        size_t o = (size_t)row * FFIP + c;
        *(uint2*)&Yh[o] = make_uint2(h0, h1);
        *(uint2*)&Yl[o] = make_uint2(l0, l1);
    }
}

// ---------------- Q prep -> bf16 hi/lo [h][Nq][64] ----------------
__global__ void prep_q_kernel(const float* __restrict__ Qin, const float* __restrict__ qs,
                              __nv_bfloat16* __restrict__ Qh, __nv_bfloat16* __restrict__ Ql,
                              int Nq, int srcStride) {
    int gw = (blockIdx.x * blockDim.x + threadIdx.x) >> 5;
    int lane = threadIdx.x & 31;
    if (gw >= NHEAD * Nq) return;
    int h = gw / Nq, n = gw % Nq;
    const float* src = Qin + (size_t)n * srcStride + h * DHEAD;
    float v0 = src[lane], v1 = src[lane + 32];
    float ss = v0 * v0 + v1 * v1;
    #pragma unroll
    for (int s = 16; s; s >>= 1) ss += __shfl_xor_sync(0xffffffffu, ss, s);
    float inv = 1.0f / fmaxf(sqrtf(ss), 1e-12f);
    float y0 = v0 * inv * qs[lane] * 8.0f;
    float y1 = v1 * inv * qs[lane + 32] * 8.0f;
    size_t base = ((size_t)h * Nq + n) * DHEAD;
    __nv_bfloat16 b0 = __float2bfloat16(y0);
    __nv_bfloat16 b1 = __float2bfloat16(y1);
    Qh[base + lane]      = b0;
    Ql[base + lane]      = __float2bfloat16(y0 - __bfloat162float(b0));
    Qh[base + lane + 32] = b1;
    Ql[base + lane + 32] = __float2bfloat16(y1 - __bfloat162float(b1));
}

// ---------------- KV prep -> bf16 hi/lo [h][NKpad][64], zero-padded ----------------
__global__ void prep_kv_kernel(const float* __restrict__ KVin, const float* __restrict__ nullp,
                               const float* __restrict__ ks,
                               __nv_bfloat16* __restrict__ Kh, __nv_bfloat16* __restrict__ Kl,
                               __nv_bfloat16* __restrict__ Vh, __nv_bfloat16* __restrict__ Vl,
                               int Nt, int NKpad, int srcStride, int vOff) {
    int NK = Nt + 1;
    int gw = (blockIdx.x * blockDim.x + threadIdx.x) >> 5;
    int lane = threadIdx.x & 31;
    if (gw >= NHEAD * NKpad) return;
    int h = gw / NKpad, j = gw % NKpad;
    size_t base = ((size_t)h * NKpad + j) * DHEAD;
    if (j >= NK) {
        __nv_bfloat16 z = __float2bfloat16(0.f);
        Kh[base + lane] = z; Kl[base + lane] = z; Vh[base + lane] = z; Vl[base + lane] = z;
        Kh[base + lane + 32] = z; Kl[base + lane + 32] = z;
        Vh[base + lane + 32] = z; Vl[base + lane + 32] = z;
        return;
    }
    float k0, k1, v0, v1;
    if (j == 0) {
        k0 = nullp[h * DHEAD + lane];
        k1 = nullp[h * DHEAD + lane + 32];
        v0 = nullp[NHEAD * DHEAD + h * DHEAD + lane];
        v1 = nullp[NHEAD * DHEAD + h * DHEAD + lane + 32];
    } else {
        const float* src = KVin + (size_t)(j - 1) * srcStride + h * DHEAD;
        k0 = src[lane];          k1 = src[lane + 32];
        v0 = src[vOff + lane];   v1 = src[vOff + lane + 32];
    }
    float ss = k0 * k0 + k1 * k1;
    #pragma unroll
    for (int s = 16; s; s >>= 1) ss += __shfl_xor_sync(0xffffffffu, ss, s);
    float inv = 1.0f / fmaxf(sqrtf(ss), 1e-12f);
    k0 = k0 * inv * ks[lane];
    k1 = k1 * inv * ks[lane + 32];
    __nv_bfloat16 b;
    b = __float2bfloat16(k0); Kh[base + lane] = b;      Kl[base + lane] = __float2bfloat16(k0 - __bfloat162float(b));
    b = __float2bfloat16(k1); Kh[base + lane + 32] = b; Kl[base + lane + 32] = __float2bfloat16(k1 - __bfloat162float(b));
    b = __float2bfloat16(v0); Vh[base + lane] = b;      Vl[base + lane] = __float2bfloat16(v0 - __bfloat162float(b));
    b = __float2bfloat16(v1); Vh[base + lane + 32] = b; Vl[base + lane + 32] = __float2bfloat16(v1 - __bfloat162float(b));
}

// ---------------- flash attention via mma.sync (unchanged from passing R14) ----------------
__global__ __launch_bounds__(256, 2)
void flash_kernel(const __nv_bfloat16* __restrict__ Qh, const __nv_bfloat16* __restrict__ Ql,
                  const __nv_bfloat16* __restrict__ Kh, const __nv_bfloat16* __restrict__ Kl,
                  const __nv_bfloat16* __restrict__ Vh, const __nv_bfloat16* __restrict__ Vl,
                  __nv_bfloat16* __restrict__ Oh, __nv_bfloat16* __restrict__ Ol,
                  int Nq, int NK, int NKpad) {
    extern __shared__ char smraw[];
    uint32_t sb = smem_u32(smraw);
    const uint32_t QHS = 0, QLS = 16384, KV0 = 32768;
    int tid = threadIdx.x, warp = tid >> 5, lane = tid & 31;
    int gid = lane >> 2, tig = lane & 3;
    int wm = warp * 16;
    int hh = blockIdx.y;
    int qb = blockIdx.x * 128;
    int srow = tid >> 3, skc = tid & 7;

    #pragma unroll
    for (int i = 0; i < 4; i++) {
        int row = srow + i * 32;
        uint32_t off = (uint32_t)row * 128 + (uint32_t)((skc ^ (row & 7)) << 4);
        size_t g = ((size_t)hh * Nq + qb + row) * DHEAD + skc * 8;
        cp16(sb + QHS + off, Qh + g);
        cp16(sb + QLS + off, Ql + g);
    }
    asm volatile("cp.async.commit_group;\n" ::: "memory");

    auto stageKV = [&](int t, int b) {
        uint32_t kvb = sb + KV0 + (uint32_t)b * 32768u;
        #pragma unroll
        for (int i = 0; i < 2; i++) {
            int row = srow + i * 32;
            uint32_t off = (uint32_t)row * 128 + (uint32_t)((skc ^ (row & 7)) << 4);
            size_t g = ((size_t)hh * NKpad + t * 64 + row) * DHEAD + skc * 8;
            cp16(kvb + off,          Kh + g);
            cp16(kvb + 8192 + off,   Kl + g);
            cp16(kvb + 16384 + off,  Vh + g);
            cp16(kvb + 24576 + off,  Vl + g);
        }
        asm volatile("cp.async.commit_group;\n" ::: "memory");
    };
    stageKV(0, 0);

    float o[8][4];
    #pragma unroll
    for (int b8 = 0; b8 < 8; b8++) o[b8][0] = o[b8][1] = o[b8][2] = o[b8][3] = 0.f;
    float mrow0 = -1e30f, mrow1 = -1e30f, lrow0 = 0.f, lrow1 = 0.f;

    int ntiles = NKpad >> 6;
    for (int t = 0; t < ntiles; t++) {
        int b = t & 1;
        asm volatile("cp.async.wait_group 0;\n" ::: "memory");
        __syncthreads();
        if (t + 1 < ntiles) stageKV(t + 1, b ^ 1);
        uint32_t kvb = sb + KV0 + (uint32_t)b * 32768u;

        float s[8][4];
        #pragma unroll
        for (int b8 = 0; b8 < 8; b8++) s[b8][0] = s[b8][1] = s[b8][2] = s[b8][3] = 0.f;
        #pragma unroll
        for (int ks = 0; ks < 4; ks++) {
            uint32_t qfh[4], qfl[4];
            {
                int row = wm + (lane & 15);
                int c = ks * 2 + (lane >> 4);
                uint32_t off = (uint32_t)row * 128 + (uint32_t)((c ^ (row & 7)) << 4);
                ldsm4(qfh, sb + QHS + off);
                ldsm4(qfl, sb + QLS + off);
            }
            #pragma unroll
            for (int nb = 0; nb < 4; nb++) {
                uint32_t kh4[4], kl4[4];
                int row = nb * 16 + (lane & 15);
                int c = ks * 2 + (lane >> 4);
                uint32_t off = (uint32_t)row * 128 + (uint32_t)((c ^ (row & 7)) << 4);
                ldsm4(kh4, kvb + off);
                ldsm4(kl4, kvb + 8192 + off);
                mma16816(s[2 * nb],     qfh, kh4[0], kh4[2]);
                mma16816(s[2 * nb],     qfl, kh4[0], kh4[2]);
                mma16816(s[2 * nb],     qfh, kl4[0], kl4[2]);
                mma16816(s[2 * nb + 1], qfh, kh4[1], kh4[3]);
                mma16816(s[2 * nb + 1], qfl, kh4[1], kh4[3]);
                mma16816(s[2 * nb + 1], qfh, kl4[1], kl4[3]);
            }
        }
        int kb = t << 6;
        if (kb + 64 > NK) {
            #pragma unroll
            for (int b8 = 0; b8 < 8; b8++) {
                int col = kb + b8 * 8 + tig * 2;
                if (col >= NK)     { s[b8][0] = -1e30f; s[b8][2] = -1e30f; }
                if (col + 1 >= NK) { s[b8][1] = -1e30f; s[b8][3] = -1e30f; }
            }
        }
        float m0 = -1e30f, m1 = -1e30f;
        #pragma unroll
        for (int b8 = 0; b8 < 8; b8++) {
            m0 = fmaxf(m0, fmaxf(s[b8][0], s[b8][1]));
            m1 = fmaxf(m1, fmaxf(s[b8][2], s[b8][3]));
        }
        m0 = fmaxf(m0, __shfl_xor_sync(0xffffffffu, m0, 1));
        m0 = fmaxf(m0, __shfl_xor_sync(0xffffffffu, m0, 2));
        m1 = fmaxf(m1, __shfl_xor_sync(0xffffffffu, m1, 1));
        m1 = fmaxf(m1, __shfl_xor_sync(0xffffffffu, m1, 2));
        float mn0 = fmaxf(mrow0, m0), mn1 = fmaxf(mrow1, m1);
        float corr0 = __expf(mrow0 - mn0), corr1 = __expf(mrow1 - mn1);
        mrow0 = mn0; mrow1 = mn1;
        float r0 = 0.f, r1 = 0.f;
        #pragma unroll
        for (int b8 = 0; b8 < 8; b8++) {
            s[b8][0] = __expf(s[b8][0] - mn0); r0 += s[b8][0];
            s[b8][1] = __expf(s[b8][1] - mn0); r0 += s[b8][1];
            s[b8][2] = __expf(s[b8][2] - mn1); r1 += s[b8][2];
            s[b8][3] = __expf(s[b8][3] - mn1); r1 += s[b8][3];
        }
        r0 += __shfl_xor_sync(0xffffffffu, r0, 1);
        r0 += __shfl_xor_sync(0xffffffffu, r0, 2);
        r1 += __shfl_xor_sync(0xffffffffu, r1, 1);
        r1 += __shfl_xor_sync(0xffffffffu, r1, 2);
        lrow0 = lrow0 * corr0 + r0;
        lrow1 = lrow1 * corr1 + r1;
        #pragma unroll
        for (int b8 = 0; b8 < 8; b8++) {
            o[b8][0] *= corr0; o[b8][1] *= corr0;
            o[b8][2] *= corr1; o[b8][3] *= corr1;
        }
        #pragma unroll
        for (int ks = 0; ks < 4; ks++) {
            uint32_t ph[4], pl[4];
            split2(s[2 * ks][0],     s[2 * ks][1],     ph[0], pl[0]);
            split2(s[2 * ks][2],     s[2 * ks][3],     ph[1], pl[1]);
            split2(s[2 * ks + 1][0], s[2 * ks + 1][1], ph[2], pl[2]);
            split2(s[2 * ks + 1][2], s[2 * ks + 1][3], ph[3], pl[3]);
            #pragma unroll
            for (int db = 0; db < 4; db++) {
                uint32_t vh4[4], vl4[4];
                int jrow = ks * 16 + (lane & 15);
                int dchunk = db * 2 + (lane >> 4);
                uint32_t off = (uint32_t)jrow * 128 + (uint32_t)((dchunk ^ (jrow & 7)) << 4);
                ldsm4t(vh4, kvb + 16384 + off);
                ldsm4t(vl4, kvb + 24576 + off);
                mma16816(o[2 * db],     ph, vh4[0], vh4[1]);
                mma16816(o[2 * db],     pl, vh4[0], vh4[1]);
                mma16816(o[2 * db],     ph, vl4[0], vl4[1]);
                mma16816(o[2 * db + 1], ph, vh4[2], vh4[3]);
                mma16816(o[2 * db + 1], pl, vh4[2], vh4[3]);
                mma16816(o[2 * db + 1], ph, vl4[2], vl4[3]);
            }
        }
    }
    float inv0 = 1.f / lrow0, inv1 = 1.f / lrow1;
    int row0 = qb + wm + gid, row1 = row0 + 8;
    #pragma unroll
    for (int b8 = 0; b8 < 8; b8++) {
        int col = hh * DHEAD + b8 * 8 + tig * 2;
        uint32_t hi, lo;
        split2(o[b8][0] * inv0, o[b8][1] * inv0, hi, lo);
        *(uint32_t*)&Oh[(size_t)row0 * DMODEL + col] = hi;
        *(uint32_t*)&Ol[(size_t)row0 * DMODEL + col] = lo;
        split2(o[b8][2] * inv1, o[b8][3] * inv1, hi, lo);
        *(uint32_t*)&Oh[(size_t)row1 * DMODEL + col] = hi;
        *(uint32_t*)&Ol[(size_t)row1 * DMODEL + col] = lo;
    }
}

// ---------------- host orchestration ----------------
extern "C" void kernel_launch(void* const* d_in, const int* in_sizes, int n_in,
                              void* d_out, int out_size) {
    (void)in_sizes; (void)n_in; (void)out_size;
    const int*   x_ids    = (const int*)d_in[0];
    const int*   cond_ids = (const int*)d_in[1];
    const float* token_emb = (const float*)d_in[2];
    const float* pos_emb   = (const float*)d_in[3];
    const float* cte       = (const float*)d_in[4];
    const float* cpe       = (const float*)d_in[5];
    const float* sa_g    = (const float*)d_in[6];
    const float* sa_wq   = (const float*)d_in[7];
    const float* sa_wkv  = (const float*)d_in[8];
    const float* sa_null = (const float*)d_in[9];
    const float* sa_qs   = (const float*)d_in[10];
    const float* sa_ks   = (const float*)d_in[11];
    const float* sa_wo   = (const float*)d_in[12];
    const float* ca_g    = (const float*)d_in[13];
    const float* ca_wq   = (const float*)d_in[14];
    const float* ca_wkv  = (const float*)d_in[15];
    const float* ca_null = (const float*)d_in[16];
    const float* ca_qs   = (const float*)d_in[17];
    const float* ca_ks   = (const float*)d_in[18];
    const float* ca_wo   = (const float*)d_in[19];
    const float* ff_g1   = (const float*)d_in[20];
    const float* ff_w1   = (const float*)d_in[21];
    const float* ff_g2   = (const float*)d_in[22];
    const float* ff_w2   = (const float*)d_in[23];
    const float* final_g  = (const float*)d_in[24];
    const float* w_logits = (const float*)d_in[25];
    float* out = (float*)d_out;

    float *H, *QKV, *Q, *KV, *HH;
    __nv_bfloat16 *WH, *WL, *XNh, *XNl, *CTXh, *CTXl, *Oh, *Ol, *GNh, *GNl;
    __nv_bfloat16 *Qbh, *Qbl, *Kbh, *Kbl, *Vbh, *Vbl;
    cudaGetSymbolAddress((void**)&H,   g_H);
    cudaGetSymbolAddress((void**)&QKV, g_QKV);
    cudaGetSymbolAddress((void**)&Q,   g_Q);
    cudaGetSymbolAddress((void**)&KV,  g_KV);
    cudaGetSymbolAddress((void**)&HH,  g_HH);
    cudaGetSymbolAddress((void**)&WH,  g_WH);
    cudaGetSymbolAddress((void**)&WL,  g_WL);
    cudaGetSymbolAddress((void**)&XNh, g_XNh);
    cudaGetSymbolAddress((void**)&XNl, g_XNl);
    cudaGetSymbolAddress((void**)&CTXh, g_CTXh);
    cudaGetSymbolAddress((void**)&CTXl, g_CTXl);
    cudaGetSymbolAddress((void**)&Oh,  g_Oh);
    cudaGetSymbolAddress((void**)&Ol,  g_Ol);
    cudaGetSymbolAddress((void**)&GNh, g_GNh);
    cudaGetSymbolAddress((void**)&GNl, g_GNl);
    cudaGetSymbolAddress((void**)&Qbh, g_Qbh);
    cudaGetSymbolAddress((void**)&Qbl, g_Qbl);
    cudaGetSymbolAddress((void**)&Kbh, g_Kbh);
    cudaGetSymbolAddress((void**)&Kbl, g_Kbl);
    cudaGetSymbolAddress((void**)&Vbh, g_Vbh);
    cudaGetSymbolAddress((void**)&Vbl, g_Vbl);

    const int FLASH_SMEM = 98304;        // 96KB
    const int GEMM_SMEM  = 73728;        // 72KB (3 x 24KB ring)
    cudaFuncSetAttribute(flash_kernel, cudaFuncAttributeMaxDynamicSharedMemorySize, FLASH_SMEM);
    cudaFuncSetAttribute(gemm_bf16_kernel, cudaFuncAttributeMaxDynamicSharedMemorySize, GEMM_SMEM);

    // ---- fused weight conversion ----
    {
        ConvTab tab;
        int cnt = 0, tiles = 0;
        auto add = [&](const float* W, long long off, int Kd, int Nd, int k_pad, int n_pad) {
            ConvEnt& e = tab.e[cnt++];
            e.W = W; e.off = off; e.K = Kd; e.N = Nd; e.kpad = k_pad;
            e.tiles_n = n_pad / 32; e.tileStart = tiles;
            tiles += (n_pad / 32) * (k_pad / 32);
        };
        for (int l = 0; l < NLAYER; l++) {
            long long lb = (long long)l * LBLK;
            add(sa_wq  + (size_t)l * DMODEL * DMODEL,     lb + W_WQ,   1024, 1024, 1024, 1024);
            add(sa_wkv + (size_t)l * DMODEL * 2 * DMODEL, lb + W_WKV,  1024, 2048, 1024, 2048);
            add(sa_wo  + (size_t)l * DMODEL * DMODEL,     lb + W_WO,   1024, 1024, 1024, 1024);
            add(ca_wq  + (size_t)l * DMODEL * DMODEL,     lb + W_CWQ,  1024, 1024, 1024, 1024);
            add(ca_wkv + (size_t)l * DMODEL * 2 * DMODEL, lb + W_CWKV, 1024, 2048, 1024, 2048);
            add(ca_wo  + (size_t)l * DMODEL * DMODEL,     lb + W_CWO,  1024, 1024, 1024, 1024);
            add(ff_w1  + (size_t)l * DMODEL * FF2,        lb + W_FF1,  1024, FF2,  1024, 5504);
            add(ff_w2  + (size_t)l * FFI * DMODEL,        lb + W_FF2,  FFI,  1024, FFIP, 1024);
        }
        add(w_logits, W_LOG, 1024, VOCAB, 1024, VOCAB);
        tab.cnt = cnt;
        convw_all_kernel<<<tiles, 256>>>(tab, WH, WL);
    }

    embed_img_kernel<<<(NTOK * DMODEL) / 256, 256>>>(x_ids, token_emb, pos_emb, H);
    embed_ctx_kernel<<<(NCTX * DMODEL / 2) / 256, 256>>>(cond_ids, cte, cpe, CTXh, CTXl);

    auto gemm = [&](const __nv_bfloat16* aH, const __nv_bfloat16* aL, size_t woff,
                    float* Cp, int M, int N, int lda, int ldb, int ktiles, int addC,
                    int gx, int gy) {
        gemm_bf16_kernel<<<dim3(gx, gy), 256, GEMM_SMEM>>>(aH, aL, WH + woff, WL + woff,
                                                           Cp, M, N, lda, ldb, ktiles, addC);
    };

    for (int l = 0; l < NLAYER; l++) {
        size_t lb = (size_t)l * LBLK;
        // ------- self attention (fused QKV projection: N = 3072) -------
        ln_kernel<<<NTOK / 8, 256>>>(H, sa_g + (size_t)l * DMODEL, XNh, XNl);
        gemm(XNh, XNl, lb + W_WQ, QKV, NTOK, 3072, 1024, 1024, 32, 0, 48, 12);
        prep_q_kernel<<<(NHEAD * NTOK + 7) / 8, 256>>>(QKV, sa_qs + l * DHEAD, Qbh, Qbl, NTOK, 3072);
        prep_kv_kernel<<<(NHEAD * NKPAD_SA + 7) / 8, 256>>>(QKV + DMODEL,
                                                            sa_null + (size_t)l * 2 * NHEAD * DHEAD,
                                                            sa_ks + l * DHEAD, Kbh, Kbl, Vbh, Vbl,
                                                            NTOK, NKPAD_SA, 3072, DMODEL);
        flash_kernel<<<dim3(NTOK / 128, NHEAD), 256, FLASH_SMEM>>>(Qbh, Qbl, Kbh, Kbl, Vbh, Vbl,
                                                                   Oh, Ol, NTOK, NTOK + 1, NKPAD_SA);
        gemm(Oh, Ol, lb + W_WO, H, NTOK, 1024, 1024, 1024, 32, 1, 16, 12);

        // ------- cross attention -------
        ln_kernel<<<NTOK / 8, 256>>>(H, ca_g + (size_t)l * DMODEL, XNh, XNl);
        gemm(XNh, XNl, lb + W_CWQ, Q, NTOK, 1024, 1024, 1024, 32, 0, 16, 12);
        gemm(CTXh, CTXl, lb + W_CWKV, KV, NCTX, 2048, 1024, 1024, 32, 0, 32, 4);
        prep_q_kernel<<<(NHEAD * NTOK + 7) / 8, 256>>>(Q, ca_qs + l * DHEAD, Qbh, Qbl, NTOK, DMODEL);
        prep_kv_kernel<<<(NHEAD * NKPAD_CA + 7) / 8, 256>>>(KV,
                                                            ca_null + (size_t)l * 2 * NHEAD * DHEAD,
                                                            ca_ks + l * DHEAD, Kbh, Kbl, Vbh, Vbl,
                                                            NCTX, NKPAD_CA, 2 * DMODEL, DMODEL);
        flash_kernel<<<dim3(NTOK / 128, NHEAD), 256, FLASH_SMEM>>>(Qbh, Qbl, Kbh, Kbl, Vbh, Vbl,
                                                                   Oh, Ol, NTOK, NCTX + 1, NKPAD_CA);
        gemm(Oh, Ol, lb + W_CWO, H, NTOK, 1024, 1024, 1024, 32, 1, 16, 12);

        // ------- GEGLU feedforward -------
        ln_kernel<<<NTOK / 8, 256>>>(H, ff_g1 + (size_t)l * DMODEL, XNh, XNl);
        gemm(XNh, XNl, lb + W_FF1, HH, NTOK, FF2, 1024, 1024, 32, 0, 86, 12);
        geglu_ln_kernel<<<NTOK, 256>>>(HH, ff_g2 + (size_t)l * FFI, GNh, GNl);
        gemm(GNh, GNl, lb + W_FF2, H, NTOK, 1024, FFIP, FFIP, 86, 1, 16, 12);
    }

    // ------- final norm + logits -------
    ln_kernel<<<NTOK / 8, 256>>>(H, final_g, XNh, XNl);
    gemm(XNh, XNl, W_LOG, out, NTOK, VOCAB, 1024, 1024, 32, 0, 128, 12);
}

// round 16
// speedup vs baseline: 1.0341x; 1.0341x over previous
#include <cuda_runtime.h>
#include <cuda_bf16.h>
#include <math.h>
#include <stdint.h>

// ---------------- model dims ----------------
#define NLAYER 4
#define DMODEL 1024
#define NHEAD  16
#define DHEAD  64
#define NTOK   1536
#define NCTX   512
#define VOCAB  8192
#define FFI    2730          // GEGLU inner
#define FF2    5460          // 2*FFI
#define FFIP   2752          // FFI padded to 64
#define NKPAD_SA 1600        // 25*64 >= NTOK+1
#define NKPAD_CA 576         // 9*64  >= NCTX+1

// ---------------- weight scratch offsets (padded, transposed [n][k] bf16) ----------------
#define W_WQ    0ull
#define W_WKV   1048576ull
#define W_WO    3145728ull
#define W_CWQ   4194304ull
#define W_CWKV  5242880ull
#define W_CWO   7340032ull
#define W_FF1   8388608ull
#define W_FF2   14024704ull
#define LBLK    16842752ull
#define W_LOG   67371008ull
#define WTOT    75759616ull

// ---------------- scratch (device globals; no allocation allowed) ----------------
__device__ float g_H  [NTOK * DMODEL];
__device__ float g_QKV[NTOK * 3 * DMODEL];
__device__ float g_Q  [NTOK * DMODEL];
__device__ float g_KV [NCTX * 2 * DMODEL];
__device__ float g_HH [NTOK * FF2];

__device__ __align__(128) __nv_bfloat16 g_WH[WTOT];
__device__ __align__(128) __nv_bfloat16 g_WL[WTOT];
__device__ __align__(128) __nv_bfloat16 g_XNh[NTOK * DMODEL],  g_XNl[NTOK * DMODEL];
__device__ __align__(128) __nv_bfloat16 g_CTXh[NCTX * DMODEL], g_CTXl[NCTX * DMODEL];
__device__ __align__(128) __nv_bfloat16 g_Oh[NTOK * DMODEL],   g_Ol[NTOK * DMODEL];
__device__ __align__(128) __nv_bfloat16 g_GNh[NTOK * FFIP],    g_GNl[NTOK * FFIP];
// attention operands, bf16 hi/lo
__device__ __align__(128) __nv_bfloat16 g_Qbh[NHEAD * NTOK * DHEAD], g_Qbl[NHEAD * NTOK * DHEAD];
__device__ __align__(128) __nv_bfloat16 g_Kbh[NHEAD * NKPAD_SA * DHEAD], g_Kbl[NHEAD * NKPAD_SA * DHEAD];
__device__ __align__(128) __nv_bfloat16 g_Vbh[NHEAD * NKPAD_SA * DHEAD], g_Vbl[NHEAD * NKPAD_SA * DHEAD];

// ---------------- helpers ----------------
__device__ __forceinline__ uint32_t smem_u32(const void* p) {
    uint32_t a;
    asm("{ .reg .u64 t; cvta.to.shared.u64 t, %1; cvt.u32.u64 %0, t; }" : "=r"(a) : "l"(p));
    return a;
}
__device__ __forceinline__ void split2(float f0, float f1, uint32_t& hi, uint32_t& lo) {
    __nv_bfloat16 h0 = __float2bfloat16(f0), h1 = __float2bfloat16(f1);
    float r0 = f0 - __bfloat162float(h0), r1 = f1 - __bfloat162float(h1);
    __nv_bfloat16 l0 = __float2bfloat16(r0), l1 = __float2bfloat16(r1);
    hi = (uint32_t)__bfloat16_as_ushort(h0) | ((uint32_t)__bfloat16_as_ushort(h1) << 16);
    lo = (uint32_t)__bfloat16_as_ushort(l0) | ((uint32_t)__bfloat16_as_ushort(l1) << 16);
}
__device__ __forceinline__ void ldsm4(uint32_t* r, uint32_t addr) {
    asm volatile("ldmatrix.sync.aligned.m8n8.x4.shared.b16 {%0,%1,%2,%3}, [%4];"
                 : "=r"(r[0]), "=r"(r[1]), "=r"(r[2]), "=r"(r[3]) : "r"(addr));
}
__device__ __forceinline__ void ldsm4t(uint32_t* r, uint32_t addr) {
    asm volatile("ldmatrix.sync.aligned.m8n8.x4.trans.shared.b16 {%0,%1,%2,%3}, [%4];"
                 : "=r"(r[0]), "=r"(r[1]), "=r"(r[2]), "=r"(r[3]) : "r"(addr));
}
__device__ __forceinline__ void mma16816(float* c, const uint32_t* a, uint32_t b0, uint32_t b1) {
    asm volatile(
        "mma.sync.aligned.m16n8k16.row.col.f32.bf16.bf16.f32 "
        "{%0,%1,%2,%3}, {%4,%5,%6,%7}, {%8,%9}, {%0,%1,%2,%3};"
        : "+f"(c[0]), "+f"(c[1]), "+f"(c[2]), "+f"(c[3])
        : "r"(a[0]), "r"(a[1]), "r"(a[2]), "r"(a[3]), "r"(b0), "r"(b1));
}
__device__ __forceinline__ void cp16(uint32_t s, const void* g) {
    asm volatile("cp.async.cg.shared.global [%0], [%1], 16;\n" :: "r"(s), "l"(g));
}

// ---------------- fused weight convert: all 33 weights in ONE launch ----------------
struct ConvEnt {
    const float* W;
    long long off;
    int K, N, kpad, tiles_n, tileStart;
};
struct ConvTab { ConvEnt e[33]; int cnt; };

__global__ void convw_all_kernel(ConvTab tab, __nv_bfloat16* __restrict__ WH,
                                 __nv_bfloat16* __restrict__ WL) {
    __shared__ float t[32][33];
    int b = blockIdx.x;
    int i = 0;
    #pragma unroll 1
    while (i + 1 < tab.cnt && tab.e[i + 1].tileStart <= b) i++;
    const ConvEnt en = tab.e[i];
    int local = b - en.tileStart;
    int nb = (local % en.tiles_n) * 32;
    int kb = (local / en.tiles_n) * 32;
    __nv_bfloat16* TH = WH + en.off;
    __nv_bfloat16* TL = WL + en.off;

    int tid = threadIdx.x;
    int tx = tid & 31, ty = tid >> 5;
    #pragma unroll
    for (int r = 0; r < 4; r++) {
        int k = kb + ty + 8 * r, n = nb + tx;
        t[ty + 8 * r][tx] = (k < en.K && n < en.N) ? en.W[(size_t)k * en.N + n] : 0.f;
    }
    __syncthreads();
    int nrow = tid >> 3, kp = tid & 7;
    #pragma unroll
    for (int w = 0; w < 2; w++) {
        int kk = (kp + 8 * w) * 2;
        float f0 = t[kk][nrow], f1 = t[kk + 1][nrow];
        uint32_t hi, lo;
        split2(f0, f1, hi, lo);
        size_t o = (size_t)(nb + nrow) * en.kpad + kb + kk;
        *(uint32_t*)&TH[o] = hi;
        *(uint32_t*)&TL[o] = lo;
    }
}

// ---------------- tensor-core GEMM (exact R14 config: 128x128, BK=64, 3x64KB ring) ----
__global__ __launch_bounds__(512, 1)
void gemm_bf16_kernel(const __nv_bfloat16* __restrict__ AH, const __nv_bfloat16* __restrict__ AL,
                      const __nv_bfloat16* __restrict__ BH, const __nv_bfloat16* __restrict__ BL,
                      float* __restrict__ C, int M, int N, int lda, int ldb,
                      int ktiles, int addC) {
    extern __shared__ char smraw[];
    uint32_t sbase = smem_u32(smraw);
    int tid = threadIdx.x, warp = tid >> 5, lane = tid & 31;
    int wm = (warp >> 2) * 32, wn = (warp & 3) * 32;
    int m0 = blockIdx.y * 128, n0 = blockIdx.x * 128;

    float acc[2][4][4];
    #pragma unroll
    for (int mi = 0; mi < 2; mi++)
        #pragma unroll
        for (int ni = 0; ni < 4; ni++)
            acc[mi][ni][0] = acc[mi][ni][1] = acc[mi][ni][2] = acc[mi][ni][3] = 0.f;

    int srow = tid >> 3, skc = tid & 7;

    auto stage = [&](int t, int buf) {
        int k0 = t << 6;
        uint32_t sb = sbase + (uint32_t)buf * 65536u;
        #pragma unroll
        for (int i = 0; i < 2; i++) {
            int row = srow + i * 64;
            uint32_t soff = (uint32_t)row * 128 + (uint32_t)((skc ^ (row & 7)) << 4);
            size_t ao = (size_t)(m0 + row) * lda + k0 + skc * 8;
            size_t bo = (size_t)(n0 + row) * ldb + k0 + skc * 8;
            cp16(sb + soff,          AH + ao);
            cp16(sb + 16384 + soff,  AL + ao);
            cp16(sb + 32768 + soff,  BH + bo);
            cp16(sb + 49152 + soff,  BL + bo);
        }
        asm volatile("cp.async.commit_group;\n" ::: "memory");
    };

    stage(0, 0);
    if (ktiles > 1) stage(1, 1);
    int bt = 0;
    for (int t = 0; t < ktiles; t++) {
        asm volatile("cp.async.wait_group 1;\n" ::: "memory");
        __syncthreads();
        if (t + 2 < ktiles) {
            int nb = bt + 2;
            if (nb >= 3) nb -= 3;
            stage(t + 2, nb);
        }

        uint32_t aHb = sbase + (uint32_t)bt * 65536u;
        uint32_t aLb = aHb + 16384, bHb = aHb + 32768, bLb = aHb + 49152;
        #pragma unroll
        for (int ks = 0; ks < 4; ks++) {
            uint32_t ah[2][4], al[2][4];
            #pragma unroll
            for (int mi = 0; mi < 2; mi++) {
                int row = wm + mi * 16 + (lane & 15);
                int c = ks * 2 + (lane >> 4);
                uint32_t off = (uint32_t)row * 128 + (uint32_t)((c ^ (row & 7)) << 4);
                ldsm4(ah[mi], aHb + off);
                ldsm4(al[mi], aLb + off);
            }
            #pragma unroll
            for (int np = 0; np < 2; np++) {
                uint32_t bh[4], bl[4];
                int row = wn + np * 16 + (lane & 15);
                int c = ks * 2 + (lane >> 4);
                uint32_t off = (uint32_t)row * 128 + (uint32_t)((c ^ (row & 7)) << 4);
                ldsm4(bh, bHb + off);
                ldsm4(bl, bLb + off);
                #pragma unroll
                for (int mi = 0; mi < 2; mi++) {
                    mma16816(acc[mi][2 * np],     ah[mi], bh[0], bh[2]);
                    mma16816(acc[mi][2 * np],     al[mi], bh[0], bh[2]);
                    mma16816(acc[mi][2 * np],     ah[mi], bl[0], bl[2]);
                    mma16816(acc[mi][2 * np + 1], ah[mi], bh[1], bh[3]);
                    mma16816(acc[mi][2 * np + 1], al[mi], bh[1], bh[3]);
                    mma16816(acc[mi][2 * np + 1], ah[mi], bl[1], bl[3]);
                }
            }
        }
        bt = (bt + 1 == 3) ? 0 : bt + 1;
    }

    int gid = lane >> 2, tig = lane & 3;
    #pragma unroll
    for (int mi = 0; mi < 2; mi++) {
        #pragma unroll
        for (int ni = 0; ni < 4; ni++) {
            int row = m0 + wm + mi * 16 + gid;
            int col = n0 + wn + ni * 8 + tig * 2;
            if (col + 1 < N && row < M) {
                float* cp = &C[(size_t)row * N + col];
                float2 v = make_float2(acc[mi][ni][0], acc[mi][ni][1]);
                if (addC) { float2 o = *(float2*)cp; v.x += o.x; v.y += o.y; }
                *(float2*)cp = v;
                float* cp8 = cp + 8 * (size_t)N;
                float2 w = make_float2(acc[mi][ni][2], acc[mi][ni][3]);
                if (addC) { float2 o = *(float2*)cp8; w.x += o.x; w.y += o.y; }
                *(float2*)cp8 = w;
            }
        }
    }
}

// ---------------- embeddings ----------------
__global__ void embed_img_kernel(const int* __restrict__ ids, const float* __restrict__ te,
                                 const float* __restrict__ pe, float* __restrict__ out) {
    int i = blockIdx.x * blockDim.x + threadIdx.x;
    if (i >= NTOK * DMODEL) return;
    int n = i >> 10, d = i & 1023;
    out[i] = te[(size_t)ids[n] * DMODEL + d] + pe[i];
}
__global__ void embed_ctx_kernel(const int* __restrict__ ids, const float* __restrict__ te,
                                 const float* __restrict__ pe,
                                 __nv_bfloat16* __restrict__ Yh, __nv_bfloat16* __restrict__ Yl) {
    int p = blockIdx.x * blockDim.x + threadIdx.x;
    if (p >= NCTX * DMODEL / 2) return;
    int i = p * 2;
    int n = i >> 10, d = i & 1023;
    const float* row = te + (size_t)ids[n] * DMODEL;
    float f0 = row[d] + pe[i];
    float f1 = row[d + 1] + pe[i + 1];
    uint32_t hi, lo;
    split2(f0, f1, hi, lo);
    *(uint32_t*)&Yh[i] = hi;
    *(uint32_t*)&Yl[i] = lo;
}

// ---------------- LayerNorm: one WARP per 1024-dim row ----------------
__global__ void ln_kernel(const float* __restrict__ X, const float* __restrict__ g,
                          __nv_bfloat16* __restrict__ Yh, __nv_bfloat16* __restrict__ Yl) {
    int row = blockIdx.x * 8 + (threadIdx.x >> 5);
    int lane = threadIdx.x & 31;
    const float* x = X + (size_t)row * DMODEL;
    float4 v[8];
    float s1 = 0.f, s2 = 0.f;
    #pragma unroll
    for (int j = 0; j < 8; j++) {
        v[j] = *(const float4*)&x[j * 128 + lane * 4];
        s1 += v[j].x + v[j].y + v[j].z + v[j].w;
        s2 += v[j].x * v[j].x + v[j].y * v[j].y + v[j].z * v[j].z + v[j].w * v[j].w;
    }
    #pragma unroll
    for (int s = 16; s; s >>= 1) {
        s1 += __shfl_xor_sync(0xffffffffu, s1, s);
        s2 += __shfl_xor_sync(0xffffffffu, s2, s);
    }
    float mean = s1 / DMODEL;
    float var  = s2 / DMODEL - mean * mean;
    float inv  = rsqrtf(var + 1e-5f);
    #pragma unroll
    for (int j = 0; j < 8; j++) {
        const float4 g4 = *(const float4*)&g[j * 128 + lane * 4];
        float y0 = (v[j].x - mean) * inv * g4.x;
        float y1 = (v[j].y - mean) * inv * g4.y;
        float y2 = (v[j].z - mean) * inv * g4.z;
        float y3 = (v[j].w - mean) * inv * g4.w;
        uint32_t h0, l0, h1, l1;
        split2(y0, y1, h0, l0);
        split2(y2, y3, h1, l1);
        size_t o = (size_t)row * DMODEL + j * 128 + lane * 4;
        *(uint2*)&Yh[o] = make_uint2(h0, h1);
        *(uint2*)&Yl[o] = make_uint2(l0, l1);
    }
}

// ---------------- fused GEGLU + LayerNorm -> bf16 hi/lo [row][FFIP] ----------------
__global__ void geglu_ln_kernel(const float* __restrict__ HH, const float* __restrict__ g2,
                                __nv_bfloat16* __restrict__ Yh, __nv_bfloat16* __restrict__ Yl) {
    int row = blockIdx.x;
    const float* h = HH + (size_t)row * FF2;
    int tid = threadIdx.x;
    __shared__ float buf[FFI];
    __shared__ float red[512];
    float s1 = 0.f, s2 = 0.f;
    for (int c = tid; c < FFI; c += 256) {
        float a = h[c], gate = h[FFI + c];
        float v = gate * (0.5f * a * (1.0f + erff(a * 0.70710678118654752f)));
        buf[c] = v; s1 += v; s2 += v * v;
    }
    red[tid] = s1; red[256 + tid] = s2;
    __syncthreads();
    for (int s = 128; s > 0; s >>= 1) {
        if (tid < s) { red[tid] += red[tid + s]; red[256 + tid] += red[256 + tid + s]; }
        __syncthreads();
    }
    float mean = red[0] / FFI;
    float var  = red[256] / FFI - mean * mean;
    float inv  = rsqrtf(var + 1e-5f);
    for (int q = tid; q < FFIP / 4; q += 256) {
        int c = q * 4;
        float y[4];
        #pragma unroll
        for (int j = 0; j < 4; j++) {
            int cc = c + j;
            y[j] = (cc < FFI) ? (buf[cc] - mean) * inv * g2[cc] : 0.f;
        }
        uint32_t h0, l0, h1, l1;
        split2(y[0], y[1], h0, l0);
        split2(y[2], y[3], h1, l1);
        size_t o = (size_t)row * FFIP + c;
        *(uint2*)&Yh[o] = make_uint2(h0, h1);
        *(uint2*)&Yl[o] = make_uint2(l0, l1);
    }
}

// ---------------- fused Q + KV prep (one launch per attention block) ----------------
__global__ void prep_qkv_kernel(const float* __restrict__ Qin, const float* __restrict__ qs,
                                __nv_bfloat16* __restrict__ Qh, __nv_bfloat16* __restrict__ Ql,
                                int Nq, int qStride,
                                const float* __restrict__ KVin, const float* __restrict__ nullp,
                                const float* __restrict__ ks,
                                __nv_bfloat16* __restrict__ Kh, __nv_bfloat16* __restrict__ Kl,
                                __nv_bfloat16* __restrict__ Vh, __nv_bfloat16* __restrict__ Vl,
                                int Nt, int NKpad, int kvStride, int vOff) {
    int gw = (blockIdx.x * blockDim.x + threadIdx.x) >> 5;
    int lane = threadIdx.x & 31;
    int nQ = NHEAD * Nq;
    if (gw < nQ) {
        int h = gw / Nq, n = gw % Nq;
        const float* src = Qin + (size_t)n * qStride + h * DHEAD;
        float v0 = src[lane], v1 = src[lane + 32];
        float ss = v0 * v0 + v1 * v1;
        #pragma unroll
        for (int s = 16; s; s >>= 1) ss += __shfl_xor_sync(0xffffffffu, ss, s);
        float inv = 1.0f / fmaxf(sqrtf(ss), 1e-12f);
        float y0 = v0 * inv * qs[lane] * 8.0f;
        float y1 = v1 * inv * qs[lane + 32] * 8.0f;
        size_t base = ((size_t)h * Nq + n) * DHEAD;
        __nv_bfloat16 b0 = __float2bfloat16(y0);
        __nv_bfloat16 b1 = __float2bfloat16(y1);
        Qh[base + lane]      = b0;
        Ql[base + lane]      = __float2bfloat16(y0 - __bfloat162float(b0));
        Qh[base + lane + 32] = b1;
        Ql[base + lane + 32] = __float2bfloat16(y1 - __bfloat162float(b1));
        return;
    }
    gw -= nQ;
    if (gw >= NHEAD * NKpad) return;
    int NKr = Nt + 1;
    int h = gw / NKpad, j = gw % NKpad;
    size_t base = ((size_t)h * NKpad + j) * DHEAD;
    if (j >= NKr) {
        __nv_bfloat16 z = __float2bfloat16(0.f);
        Kh[base + lane] = z; Kl[base + lane] = z; Vh[base + lane] = z; Vl[base + lane] = z;
        Kh[base + lane + 32] = z; Kl[base + lane + 32] = z;
        Vh[base + lane + 32] = z; Vl[base + lane + 32] = z;
        return;
    }
    float k0, k1, v0, v1;
    if (j == 0) {
        k0 = nullp[h * DHEAD + lane];
        k1 = nullp[h * DHEAD + lane + 32];
        v0 = nullp[NHEAD * DHEAD + h * DHEAD + lane];
        v1 = nullp[NHEAD * DHEAD + h * DHEAD + lane + 32];
    } else {
        const float* src = KVin + (size_t)(j - 1) * kvStride + h * DHEAD;
        k0 = src[lane];          k1 = src[lane + 32];
        v0 = src[vOff + lane];   v1 = src[vOff + lane + 32];
    }
    float ss = k0 * k0 + k1 * k1;
    #pragma unroll
    for (int s = 16; s; s >>= 1) ss += __shfl_xor_sync(0xffffffffu, ss, s);
    float inv = 1.0f / fmaxf(sqrtf(ss), 1e-12f);
    k0 = k0 * inv * ks[lane];
    k1 = k1 * inv * ks[lane + 32];
    __nv_bfloat16 b;
    b = __float2bfloat16(k0); Kh[base + lane] = b;      Kl[base + lane] = __float2bfloat16(k0 - __bfloat162float(b));
    b = __float2bfloat16(k1); Kh[base + lane + 32] = b; Kl[base + lane + 32] = __float2bfloat16(k1 - __bfloat162float(b));
    b = __float2bfloat16(v0); Vh[base + lane] = b;      Vl[base + lane] = __float2bfloat16(v0 - __bfloat162float(b));
    b = __float2bfloat16(v1); Vh[base + lane + 32] = b; Vl[base + lane + 32] = __float2bfloat16(v1 - __bfloat162float(b));
}

// ---------------- flash attention via mma.sync (unchanged from passing R14) ----------------
__global__ __launch_bounds__(256, 2)
void flash_kernel(const __nv_bfloat16* __restrict__ Qh, const __nv_bfloat16* __restrict__ Ql,
                  const __nv_bfloat16* __restrict__ Kh, const __nv_bfloat16* __restrict__ Kl,
                  const __nv_bfloat16* __restrict__ Vh, const __nv_bfloat16* __restrict__ Vl,
                  __nv_bfloat16* __restrict__ Oh, __nv_bfloat16* __restrict__ Ol,
                  int Nq, int NK, int NKpad) {
    extern __shared__ char smraw[];
    uint32_t sb = smem_u32(smraw);
    const uint32_t QHS = 0, QLS = 16384, KV0 = 32768;
    int tid = threadIdx.x, warp = tid >> 5, lane = tid & 31;
    int gid = lane >> 2, tig = lane & 3;
    int wm = warp * 16;
    int hh = blockIdx.y;
    int qb = blockIdx.x * 128;
    int srow = tid >> 3, skc = tid & 7;

    #pragma unroll
    for (int i = 0; i < 4; i++) {
        int row = srow + i * 32;
        uint32_t off = (uint32_t)row * 128 + (uint32_t)((skc ^ (row & 7)) << 4);
        size_t g = ((size_t)hh * Nq + qb + row) * DHEAD + skc * 8;
        cp16(sb + QHS + off, Qh + g);
        cp16(sb + QLS + off, Ql + g);
    }
    asm volatile("cp.async.commit_group;\n" ::: "memory");

    auto stageKV = [&](int t, int b) {
        uint32_t kvb = sb + KV0 + (uint32_t)b * 32768u;
        #pragma unroll
        for (int i = 0; i < 2; i++) {
            int row = srow + i * 32;
            uint32_t off = (uint32_t)row * 128 + (uint32_t)((skc ^ (row & 7)) << 4);
            size_t g = ((size_t)hh * NKpad + t * 64 + row) * DHEAD + skc * 8;
            cp16(kvb + off,          Kh + g);
            cp16(kvb + 8192 + off,   Kl + g);
            cp16(kvb + 16384 + off,  Vh + g);
            cp16(kvb + 24576 + off,  Vl + g);
        }
        asm volatile("cp.async.commit_group;\n" ::: "memory");
    };
    stageKV(0, 0);

    float o[8][4];
    #pragma unroll
    for (int b8 = 0; b8 < 8; b8++) o[b8][0] = o[b8][1] = o[b8][2] = o[b8][3] = 0.f;
    float mrow0 = -1e30f, mrow1 = -1e30f, lrow0 = 0.f, lrow1 = 0.f;

    int ntiles = NKpad >> 6;
    for (int t = 0; t < ntiles; t++) {
        int b = t & 1;
        asm volatile("cp.async.wait_group 0;\n" ::: "memory");
        __syncthreads();
        if (t + 1 < ntiles) stageKV(t + 1, b ^ 1);
        uint32_t kvb = sb + KV0 + (uint32_t)b * 32768u;

        float s[8][4];
        #pragma unroll
        for (int b8 = 0; b8 < 8; b8++) s[b8][0] = s[b8][1] = s[b8][2] = s[b8][3] = 0.f;
        #pragma unroll
        for (int ks = 0; ks < 4; ks++) {
            uint32_t qfh[4], qfl[4];
            {
                int row = wm + (lane & 15);
                int c = ks * 2 + (lane >> 4);
                uint32_t off = (uint32_t)row * 128 + (uint32_t)((c ^ (row & 7)) << 4);
                ldsm4(qfh, sb + QHS + off);
                ldsm4(qfl, sb + QLS + off);
            }
            #pragma unroll
            for (int nb = 0; nb < 4; nb++) {
                uint32_t kh4[4], kl4[4];
                int row = nb * 16 + (lane & 15);
                int c = ks * 2 + (lane >> 4);
                uint32_t off = (uint32_t)row * 128 + (uint32_t)((c ^ (row & 7)) << 4);
                ldsm4(kh4, kvb + off);
                ldsm4(kl4, kvb + 8192 + off);
                mma16816(s[2 * nb],     qfh, kh4[0], kh4[2]);
                mma16816(s[2 * nb],     qfl, kh4[0], kh4[2]);
                mma16816(s[2 * nb],     qfh, kl4[0], kl4[2]);
                mma16816(s[2 * nb + 1], qfh, kh4[1], kh4[3]);
                mma16816(s[2 * nb + 1], qfl, kh4[1], kh4[3]);
                mma16816(s[2 * nb + 1], qfh, kl4[1], kl4[3]);
            }
        }
        int kb = t << 6;
        if (kb + 64 > NK) {
            #pragma unroll
            for (int b8 = 0; b8 < 8; b8++) {
                int col = kb + b8 * 8 + tig * 2;
                if (col >= NK)     { s[b8][0] = -1e30f; s[b8][2] = -1e30f; }
                if (col + 1 >= NK) { s[b8][1] = -1e30f; s[b8][3] = -1e30f; }
            }
        }
        float m0 = -1e30f, m1 = -1e30f;
        #pragma unroll
        for (int b8 = 0; b8 < 8; b8++) {
            m0 = fmaxf(m0, fmaxf(s[b8][0], s[b8][1]));
            m1 = fmaxf(m1, fmaxf(s[b8][2], s[b8][3]));
        }
        m0 = fmaxf(m0, __shfl_xor_sync(0xffffffffu, m0, 1));
        m0 = fmaxf(m0, __shfl_xor_sync(0xffffffffu, m0, 2));
        m1 = fmaxf(m1, __shfl_xor_sync(0xffffffffu, m1, 1));
        m1 = fmaxf(m1, __shfl_xor_sync(0xffffffffu, m1, 2));
        float mn0 = fmaxf(mrow0, m0), mn1 = fmaxf(mrow1, m1);
        float corr0 = __expf(mrow0 - mn0), corr1 = __expf(mrow1 - mn1);
        mrow0 = mn0; mrow1 = mn1;
        float r0 = 0.f, r1 = 0.f;
        #pragma unroll
        for (int b8 = 0; b8 < 8; b8++) {
            s[b8][0] = __expf(s[b8][0] - mn0); r0 += s[b8][0];
            s[b8][1] = __expf(s[b8][1] - mn0); r0 += s[b8][1];
            s[b8][2] = __expf(s[b8][2] - mn1); r1 += s[b8][2];
            s[b8][3] = __expf(s[b8][3] - mn1); r1 += s[b8][3];
        }
        r0 += __shfl_xor_sync(0xffffffffu, r0, 1);
        r0 += __shfl_xor_sync(0xffffffffu, r0, 2);
        r1 += __shfl_xor_sync(0xffffffffu, r1, 1);
        r1 += __shfl_xor_sync(0xffffffffu, r1, 2);
        lrow0 = lrow0 * corr0 + r0;
        lrow1 = lrow1 * corr1 + r1;
        #pragma unroll
        for (int b8 = 0; b8 < 8; b8++) {
            o[b8][0] *= corr0; o[b8][1] *= corr0;
            o[b8][2] *= corr1; o[b8][3] *= corr1;
        }
        #pragma unroll
        for (int ks = 0; ks < 4; ks++) {
            uint32_t ph[4], pl[4];
            split2(s[2 * ks][0],     s[2 * ks][1],     ph[0], pl[0]);
            split2(s[2 * ks][2],     s[2 * ks][3],     ph[1], pl[1]);
            split2(s[2 * ks + 1][0], s[2 * ks + 1][1], ph[2], pl[2]);
            split2(s[2 * ks + 1][2], s[2 * ks + 1][3], ph[3], pl[3]);
            #pragma unroll
            for (int db = 0; db < 4; db++) {
                uint32_t vh4[4], vl4[4];
                int jrow = ks * 16 + (lane & 15);
                int dchunk = db * 2 + (lane >> 4);
                uint32_t off = (uint32_t)jrow * 128 + (uint32_t)((dchunk ^ (jrow & 7)) << 4);
                ldsm4t(vh4, kvb + 16384 + off);
                ldsm4t(vl4, kvb + 24576 + off);
                mma16816(o[2 * db],     ph, vh4[0], vh4[1]);
                mma16816(o[2 * db],     pl, vh4[0], vh4[1]);
                mma16816(o[2 * db],     ph, vl4[0], vl4[1]);
                mma16816(o[2 * db + 1], ph, vh4[2], vh4[3]);
                mma16816(o[2 * db + 1], pl, vh4[2], vh4[3]);
                mma16816(o[2 * db + 1], ph, vl4[2], vl4[3]);
            }
        }
    }
    float inv0 = 1.f / lrow0, inv1 = 1.f / lrow1;
    int row0 = qb + wm + gid, row1 = row0 + 8;
    #pragma unroll
    for (int b8 = 0; b8 < 8; b8++) {
        int col = hh * DHEAD + b8 * 8 + tig * 2;
        uint32_t hi, lo;
        split2(o[b8][0] * inv0, o[b8][1] * inv0, hi, lo);
        *(uint32_t*)&Oh[(size_t)row0 * DMODEL + col] = hi;
        *(uint32_t*)&Ol[(size_t)row0 * DMODEL + col] = lo;
        split2(o[b8][2] * inv1, o[b8][3] * inv1, hi, lo);
        *(uint32_t*)&Oh[(size_t)row1 * DMODEL + col] = hi;
        *(uint32_t*)&Ol[(size_t)row1 * DMODEL + col] = lo;
    }
}

// ---------------- host orchestration ----------------
extern "C" void kernel_launch(void* const* d_in, const int* in_sizes, int n_in,
                              void* d_out, int out_size) {
    (void)in_sizes; (void)n_in; (void)out_size;
    const int*   x_ids    = (const int*)d_in[0];
    const int*   cond_ids = (const int*)d_in[1];
    const float* token_emb = (const float*)d_in[2];
    const float* pos_emb   = (const float*)d_in[3];
    const float* cte       = (const float*)d_in[4];
    const float* cpe       = (const float*)d_in[5];
    const float* sa_g    = (const float*)d_in[6];
    const float* sa_wq   = (const float*)d_in[7];
    const float* sa_wkv  = (const float*)d_in[8];
    const float* sa_null = (const float*)d_in[9];
    const float* sa_qs   = (const float*)d_in[10];
    const float* sa_ks   = (const float*)d_in[11];
    const float* sa_wo   = (const float*)d_in[12];
    const float* ca_g    = (const float*)d_in[13];
    const float* ca_wq   = (const float*)d_in[14];
    const float* ca_wkv  = (const float*)d_in[15];
    const float* ca_null = (const float*)d_in[16];
    const float* ca_qs   = (const float*)d_in[17];
    const float* ca_ks   = (const float*)d_in[18];
    const float* ca_wo   = (const float*)d_in[19];
    const float* ff_g1   = (const float*)d_in[20];
    const float* ff_w1   = (const float*)d_in[21];
    const float* ff_g2   = (const float*)d_in[22];
    const float* ff_w2   = (const float*)d_in[23];
    const float* final_g  = (const float*)d_in[24];
    const float* w_logits = (const float*)d_in[25];
    float* out = (float*)d_out;

    float *H, *QKV, *Q, *KV, *HH;
    __nv_bfloat16 *WH, *WL, *XNh, *XNl, *CTXh, *CTXl, *Oh, *Ol, *GNh, *GNl;
    __nv_bfloat16 *Qbh, *Qbl, *Kbh, *Kbl, *Vbh, *Vbl;
    cudaGetSymbolAddress((void**)&H,   g_H);
    cudaGetSymbolAddress((void**)&QKV, g_QKV);
    cudaGetSymbolAddress((void**)&Q,   g_Q);
    cudaGetSymbolAddress((void**)&KV,  g_KV);
    cudaGetSymbolAddress((void**)&HH,  g_HH);
    cudaGetSymbolAddress((void**)&WH,  g_WH);
    cudaGetSymbolAddress((void**)&WL,  g_WL);
    cudaGetSymbolAddress((void**)&XNh, g_XNh);
    cudaGetSymbolAddress((void**)&XNl, g_XNl);
    cudaGetSymbolAddress((void**)&CTXh, g_CTXh);
    cudaGetSymbolAddress((void**)&CTXl, g_CTXl);
    cudaGetSymbolAddress((void**)&Oh,  g_Oh);
    cudaGetSymbolAddress((void**)&Ol,  g_Ol);
    cudaGetSymbolAddress((void**)&GNh, g_GNh);
    cudaGetSymbolAddress((void**)&GNl, g_GNl);
    cudaGetSymbolAddress((void**)&Qbh, g_Qbh);
    cudaGetSymbolAddress((void**)&Qbl, g_Qbl);
    cudaGetSymbolAddress((void**)&Kbh, g_Kbh);
    cudaGetSymbolAddress((void**)&Kbl, g_Kbl);
    cudaGetSymbolAddress((void**)&Vbh, g_Vbh);
    cudaGetSymbolAddress((void**)&Vbl, g_Vbl);

    const int FLASH_SMEM = 98304;        // 96KB
    const int GEMM_SMEM  = 196608;       // 192KB (3 x 64KB ring)
    cudaFuncSetAttribute(flash_kernel, cudaFuncAttributeMaxDynamicSharedMemorySize, FLASH_SMEM);
    cudaFuncSetAttribute(gemm_bf16_kernel, cudaFuncAttributeMaxDynamicSharedMemorySize, GEMM_SMEM);

    // ---- fused weight conversion ----
    {
        ConvTab tab;
        int cnt = 0, tiles = 0;
        auto add = [&](const float* W, long long off, int Kd, int Nd, int k_pad, int n_pad) {
            ConvEnt& e = tab.e[cnt++];
            e.W = W; e.off = off; e.K = Kd; e.N = Nd; e.kpad = k_pad;
            e.tiles_n = n_pad / 32; e.tileStart = tiles;
            tiles += (n_pad / 32) * (k_pad / 32);
        };
        for (int l = 0; l < NLAYER; l++) {
            long long lb = (long long)l * LBLK;
            add(sa_wq  + (size_t)l * DMODEL * DMODEL,     lb + W_WQ,   1024, 1024, 1024, 1024);
            add(sa_wkv + (size_t)l * DMODEL * 2 * DMODEL, lb + W_WKV,  1024, 2048, 1024, 2048);
            add(sa_wo  + (size_t)l * DMODEL * DMODEL,     lb + W_WO,   1024, 1024, 1024, 1024);
            add(ca_wq  + (size_t)l * DMODEL * DMODEL,     lb + W_CWQ,  1024, 1024, 1024, 1024);
            add(ca_wkv + (size_t)l * DMODEL * 2 * DMODEL, lb + W_CWKV, 1024, 2048, 1024, 2048);
            add(ca_wo  + (size_t)l * DMODEL * DMODEL,     lb + W_CWO,  1024, 1024, 1024, 1024);
            add(ff_w1  + (size_t)l * DMODEL * FF2,        lb + W_FF1,  1024, FF2,  1024, 5504);
            add(ff_w2  + (size_t)l * FFI * DMODEL,        lb + W_FF2,  FFI,  1024, FFIP, 1024);
        }
        add(w_logits, W_LOG, 1024, VOCAB, 1024, VOCAB);
        tab.cnt = cnt;
        convw_all_kernel<<<tiles, 256>>>(tab, WH, WL);
    }

    embed_img_kernel<<<(NTOK * DMODEL) / 256, 256>>>(x_ids, token_emb, pos_emb, H);
    embed_ctx_kernel<<<(NCTX * DMODEL / 2) / 256, 256>>>(cond_ids, cte, cpe, CTXh, CTXl);

    auto gemm = [&](const __nv_bfloat16* aH, const __nv_bfloat16* aL, size_t woff,
                    float* Cp, int M, int N, int lda, int ldb, int ktiles, int addC,
                    int gx, int gy) {
        gemm_bf16_kernel<<<dim3(gx, gy), 512, GEMM_SMEM>>>(aH, aL, WH + woff, WL + woff,
                                                           Cp, M, N, lda, ldb, ktiles, addC);
    };

    const int PREP_SA_BLKS = (NHEAD * (NTOK + NKPAD_SA) + 7) / 8;
    const int PREP_CA_BLKS = (NHEAD * (NTOK + NKPAD_CA) + 7) / 8;

    for (int l = 0; l < NLAYER; l++) {
        size_t lb = (size_t)l * LBLK;
        // ------- self attention (fused QKV projection: N = 3072) -------
        ln_kernel<<<NTOK / 8, 256>>>(H, sa_g + (size_t)l * DMODEL, XNh, XNl);
        gemm(XNh, XNl, lb + W_WQ, QKV, NTOK, 3072, 1024, 1024, 16, 0, 24, 12);
        prep_qkv_kernel<<<PREP_SA_BLKS, 256>>>(QKV, sa_qs + l * DHEAD, Qbh, Qbl, NTOK, 3072,
                                               QKV + DMODEL,
                                               sa_null + (size_t)l * 2 * NHEAD * DHEAD,
                                               sa_ks + l * DHEAD, Kbh, Kbl, Vbh, Vbl,
                                               NTOK, NKPAD_SA, 3072, DMODEL);
        flash_kernel<<<dim3(NTOK / 128, NHEAD), 256, FLASH_SMEM>>>(Qbh, Qbl, Kbh, Kbl, Vbh, Vbl,
                                                                   Oh, Ol, NTOK, NTOK + 1, NKPAD_SA);
        gemm(Oh, Ol, lb + W_WO, H, NTOK, 1024, 1024, 1024, 16, 1, 8, 12);

        // ------- cross attention -------
        ln_kernel<<<NTOK / 8, 256>>>(H, ca_g + (size_t)l * DMODEL, XNh, XNl);
        gemm(XNh, XNl, lb + W_CWQ, Q, NTOK, 1024, 1024, 1024, 16, 0, 8, 12);
        gemm(CTXh, CTXl, lb + W_CWKV, KV, NCTX, 2048, 1024, 1024, 16, 0, 16, 4);
        prep_qkv_kernel<<<PREP_CA_BLKS, 256>>>(Q, ca_qs + l * DHEAD, Qbh, Qbl, NTOK, DMODEL,
                                               KV,
                                               ca_null + (size_t)l * 2 * NHEAD * DHEAD,
                                               ca_ks + l * DHEAD, Kbh, Kbl, Vbh, Vbl,
                                               NCTX, NKPAD_CA, 2 * DMODEL, DMODEL);
        flash_kernel<<<dim3(NTOK / 128, NHEAD), 256, FLASH_SMEM>>>(Qbh, Qbl, Kbh, Kbl, Vbh, Vbl,
                                                                   Oh, Ol, NTOK, NCTX + 1, NKPAD_CA);
        gemm(Oh, Ol, lb + W_CWO, H, NTOK, 1024, 1024, 1024, 16, 1, 8, 12);

        // ------- GEGLU feedforward -------
        ln_kernel<<<NTOK / 8, 256>>>(H, ff_g1 + (size_t)l * DMODEL, XNh, XNl);
        gemm(XNh, XNl, lb + W_FF1, HH, NTOK, FF2, 1024, 1024, 16, 0, 43, 12);
        geglu_ln_kernel<<<NTOK, 256>>>(HH, ff_g2 + (size_t)l * FFI, GNh, GNl);
        gemm(GNh, GNl, lb + W_FF2, H, NTOK, 1024, FFIP, FFIP, 43, 1, 8, 12);
    }

    // ------- final norm + logits -------
    ln_kernel<<<NTOK / 8, 256>>>(H, final_g, XNh, XNl);
    gemm(XNh, XNl, W_LOG, out, NTOK, VOCAB, 1024, 1024, 16, 0, 64, 12);
}